// round 8
// baseline (speedup 1.0000x reference)
#include <cuda_runtime.h>
#include <cuda_bf16.h>
#include <math.h>

#define NN 8192
#define EE 262144
#define INC 64
#define DK 192      // IN_C*K = OUT_C*K
#define GG 64
#define NC 10

// ---------------- static scratch ----------------
__device__ int   g_is64;                  // 1 if index tensors are int64, 0 if int32
__device__ int   g_degi[NN];
__device__ float g_dinv[NN];
__device__ int   g_rowstart[NN + 1];
__device__ int   g_rowpos[NN];
__device__ __align__(16) int   g_col[EE];
__device__ __align__(16) float g_val[EE];
__device__ __align__(16) float g_H2[NN * INC];
__device__ __align__(16) float g_H3[NN * INC];
__device__ __align__(16) float g_H[NN * DK];
__device__ __align__(16) float g_Wmt[DK * DK];   // transposed masked/scaled weight: [k][o]
__device__ float g_csum[DK], g_csumsq[DK], g_mean[DK], g_rstd[DK];
__device__ __align__(16) float g_Hsum[GG * DK];
__device__ __align__(16) unsigned g_Hmax[GG * DK];
__device__ float g_cnt[GG];
__device__ __align__(16) float g_Hg[GG * 576];
__device__ __align__(16) float g_xo[GG * 576];
__device__ __align__(16) float g_w1t[576 * 384];
__device__ __align__(16) float g_w2t[384 * 192];
__device__ __align__(16) float g_o1[GG * 384];
__device__ __align__(16) float g_o2[GG * 192];

// index accessor: handles both int32 and int64 on-disk layouts
__device__ __forceinline__ int idx_at(const void* p, long long i) {
    if (g_is64) return (int)(((const long long*)p)[i]);
    return ((const int*)p)[i];
}

// ---------------- kernels ----------------
// Detect whether index tensors are int64 or int32. Values are < 8192, so for
// genuine int64 little-endian data the high 32-bit word of each element is 0.
// For int32 data read as int64, the "high word" is the next index (~never 0).
__global__ void detect_kernel(const void* ei) {
    const int* p = (const int*)ei;
    int zeros = 0;
    for (int i = 0; i < 64; i++)
        if (p[2 * i + 1] == 0) zeros++;
    g_is64 = (zeros >= 48) ? 1 : 0;
}

__global__ void zero_kernel() {
    int i = blockIdx.x * 256 + threadIdx.x;
    if (i < NN) { g_degi[i] = 0; g_rowpos[i] = 0; }
    if (i < DK) { g_csum[i] = 0.f; g_csumsq[i] = 0.f; }
    if (i < GG * DK) { g_Hsum[i] = 0.f; g_Hmax[i] = 0x00800000u; }  // map(-FLT_MAX)
    if (i < GG) g_cnt[i] = 0.f;
}

__global__ void deg_kernel(const void* __restrict__ ei) {
    int e = blockIdx.x * 256 + threadIdx.x;
    if (e < EE) atomicAdd(&g_degi[idx_at(ei, e)], 1);
}

__global__ void dinv_kernel() {
    int i = blockIdx.x * 256 + threadIdx.x;
    if (i < NN) {
        int d = g_degi[i];
        g_dinv[i] = (d > 0) ? rsqrtf((float)d) : 0.f;
    }
}

// single block, 1024 threads, 8 elems each -> exclusive prefix over 8192 degrees
__global__ void scan_kernel() {
    __shared__ int sh[1024];
    int t = threadIdx.x;
    int base = t * 8;
    int loc[8];
    int s = 0;
    #pragma unroll
    for (int i = 0; i < 8; i++) { loc[i] = s; s += g_degi[base + i]; }
    sh[t] = s;
    __syncthreads();
    for (int off = 1; off < 1024; off <<= 1) {
        int v = (t >= off) ? sh[t - off] : 0;
        __syncthreads();
        sh[t] += v;
        __syncthreads();
    }
    int offset = (t > 0) ? sh[t - 1] : 0;
    #pragma unroll
    for (int i = 0; i < 8; i++) g_rowstart[base + i] = offset + loc[i];
    if (t == 1023) g_rowstart[NN] = sh[1023];
}

__global__ void csr_kernel(const void* __restrict__ ei) {
    int e = blockIdx.x * 256 + threadIdx.x;
    if (e >= EE) return;
    int r = idx_at(ei, e);
    int c = idx_at(ei, (long long)EE + e);
    int pos = atomicAdd(&g_rowpos[r], 1);
    int at = g_rowstart[r] + pos;
    g_col[at] = c;
    g_val[at] = -g_dinv[r] * g_dinv[c];
}

// out = L @ in = in + scatter(vals * in[col]).  warp per row, float2 per lane.
template <int PASS>
__global__ void spmm_kernel(const float* __restrict__ x) {
    const float* hin  = (PASS == 0) ? x : (const float*)g_H2;
    float*       hout = (PASS == 0) ? g_H2 : g_H3;
    int warp = threadIdx.x >> 5, lane = threadIdx.x & 31;
    int r = blockIdx.x * 8 + warp;
    const float2* in2 = (const float2*)hin;
    float2 acc = in2[r * 32 + lane];
    int s = g_rowstart[r], e = g_rowstart[r + 1];
    for (int base = s; base < e; base += 32) {
        int j = base + lane;
        int c = 0; float v = 0.f;
        if (j < e) { c = g_col[j]; v = g_val[j]; }
        int m = min(32, e - base);
        for (int q = 0; q < m; q++) {
            int cc = __shfl_sync(0xffffffffu, c, q);
            float vv = __shfl_sync(0xffffffffu, v, q);
            float2 xv = in2[cc * 32 + lane];
            acc.x += vv * xv.x;
            acc.y += vv * xv.y;
        }
    }
    ((float2*)hout)[r * 32 + lane] = acc;
}

// spectral norm + mask -> g_Wmt (transposed).  one block, 256 threads.
__global__ void wprep_kernel(const float* __restrict__ W, const float* __restrict__ u) {
    __shared__ float v[DK];
    __shared__ float red[256];
    __shared__ float s_nrm, s_inv;
    int t = threadIdx.x;
    if (t < DK) {
        float a = 0.f;
        for (int i = 0; i < DK; i++) a += W[i * DK + t] * u[i];
        v[t] = a;
    }
    __syncthreads();
    red[t] = (t < DK) ? v[t] * v[t] : 0.f;
    __syncthreads();
    for (int s = 128; s > 0; s >>= 1) { if (t < s) red[t] += red[t + s]; __syncthreads(); }
    if (t == 0) s_nrm = sqrtf(red[0]) + 1e-12f;
    __syncthreads();
    if (t < DK) v[t] /= s_nrm;
    __syncthreads();
    float p = 0.f;
    if (t < DK) {
        float a = 0.f;
        for (int j = 0; j < DK; j++) a += W[t * DK + j] * v[j];
        p = a * u[t];
    }
    red[t] = p;
    __syncthreads();
    for (int s = 128; s > 0; s >>= 1) { if (t < s) red[t] += red[t + s]; __syncthreads(); }
    if (t == 0) s_inv = 1.0f / red[0];
    __syncthreads();
    for (int idx = t; idx < DK * DK; idx += 256) {
        int o = idx / DK, k = idx - o * DK;
        float mv = (k < 64 * ((o >> 6) + 1)) ? W[idx] * s_inv : 0.f;
        g_Wmt[k * DK + o] = mv;
    }
}

// H[n,o] = sum_k Hcat[n,k] * Wm[o,k] + b[o], mask exploited via kmax per col-tile.
// BM=64 BN=64 BK=16, 256 threads, 4x4 microtile.
__global__ void gemm_kernel(const float* __restrict__ x, const float* __restrict__ bias) {
    __shared__ __align__(16) float As[16][68];
    __shared__ __align__(16) float Bs[16][68];
    int bx = blockIdx.x, by = blockIdx.y;
    int t = threadIdx.x;
    int kmax = 64 * (bx + 1);
    int tx = t & 15, ty = t >> 4;
    int row0 = by * 64;
    float acc[4][4];
    #pragma unroll
    for (int i = 0; i < 4; i++)
        #pragma unroll
        for (int j = 0; j < 4; j++) acc[i][j] = 0.f;

    int ar = t >> 2, ak4 = t & 3;
    int bo = t & 63, bk = t >> 6;

    for (int k0 = 0; k0 < kmax; k0 += 16) {
        const float* A = (k0 < 64) ? x : (k0 < 128) ? (const float*)g_H2 : (const float*)g_H3;
        int kl = k0 & 63;
        float4 av = *(const float4*)&A[(row0 + ar) * 64 + kl + ak4 * 4];
        As[ak4 * 4 + 0][ar] = av.x;
        As[ak4 * 4 + 1][ar] = av.y;
        As[ak4 * 4 + 2][ar] = av.z;
        As[ak4 * 4 + 3][ar] = av.w;
        #pragma unroll
        for (int i = 0; i < 4; i++) {
            int kk = bk * 4 + i;
            Bs[kk][bo] = g_Wmt[(k0 + kk) * DK + bx * 64 + bo];
        }
        __syncthreads();
        #pragma unroll
        for (int kk = 0; kk < 16; kk++) {
            float4 a = *(float4*)&As[kk][ty * 4];
            float4 bb = *(float4*)&Bs[kk][tx * 4];
            acc[0][0] += a.x * bb.x; acc[0][1] += a.x * bb.y; acc[0][2] += a.x * bb.z; acc[0][3] += a.x * bb.w;
            acc[1][0] += a.y * bb.x; acc[1][1] += a.y * bb.y; acc[1][2] += a.y * bb.z; acc[1][3] += a.y * bb.w;
            acc[2][0] += a.z * bb.x; acc[2][1] += a.z * bb.y; acc[2][2] += a.z * bb.z; acc[2][3] += a.z * bb.w;
            acc[3][0] += a.w * bb.x; acc[3][1] += a.w * bb.y; acc[3][2] += a.w * bb.z; acc[3][3] += a.w * bb.w;
        }
        __syncthreads();
    }
    float4 bv = *(const float4*)&bias[bx * 64 + tx * 4];
    #pragma unroll
    for (int i = 0; i < 4; i++) {
        int r = row0 + ty * 4 + i;
        float* dst = &g_H[r * DK + bx * 64 + tx * 4];
        dst[0] = acc[i][0] + bv.x;
        dst[1] = acc[i][1] + bv.y;
        dst[2] = acc[i][2] + bv.z;
        dst[3] = acc[i][3] + bv.w;
    }
}

__global__ void bnstats_kernel() {  // grid 64, block 192
    int c = threadIdx.x;
    int r0 = blockIdx.x * 128;
    float s = 0.f, ss = 0.f;
    for (int i = 0; i < 128; i++) {
        float h = g_H[(r0 + i) * DK + c];
        s += h; ss += h * h;
    }
    atomicAdd(&g_csum[c], s);
    atomicAdd(&g_csumsq[c], ss);
}

__global__ void bnfin_kernel() {  // 1 block, 192 threads
    int c = threadIdx.x;
    float m = g_csum[c] * (1.f / NN);
    float v = g_csumsq[c] * (1.f / NN) - m * m;
    g_mean[c] = m;
    g_rstd[c] = rsqrtf(v + 1e-5f);
}

__global__ void pool_kernel(const void* __restrict__ batch,
                            const float* __restrict__ gamma,
                            const float* __restrict__ beta) {
    int id = blockIdx.x * 256 + threadIdx.x;   // < NN*DK
    int r = id / DK, c = id - r * DK;
    int g = idx_at(batch, r);
    float val = gamma[c] * (g_H[id] - g_mean[c]) * g_rstd[c] + beta[c];
    atomicAdd(&g_Hsum[g * DK + c], val);
    unsigned key = __float_as_uint(val);
    key = (key & 0x80000000u) ? ~key : (key | 0x80000000u);
    atomicMax(&g_Hmax[g * DK + c], key);
    if (c == 0) atomicAdd(&g_cnt[g], 1.f);
}

__global__ void hg_kernel() {
    int id = blockIdx.x * 256 + threadIdx.x;
    if (id >= GG * 576) return;
    int g = id / 576, c = id - g * 576;
    float v;
    if (c < DK) v = g_Hsum[g * DK + c] / fmaxf(g_cnt[g], 1.f);
    else if (c < 2 * DK) v = g_Hsum[g * DK + c - DK];
    else {
        unsigned k = g_Hmax[g * DK + c - 2 * DK];
        unsigned bits = (k & 0x80000000u) ? (k & 0x7fffffffu) : ~k;
        v = __uint_as_float(bits);
    }
    g_Hg[id] = v;
}

__global__ void bn2_kernel(const float* __restrict__ gamma2, const float* __restrict__ beta2) {
    int c = threadIdx.x;  // 576
    float s = 0.f, ss = 0.f;
    for (int g = 0; g < GG; g++) {
        float v = g_Hg[g * 576 + c];
        s += v; ss += v * v;
    }
    float m = s * (1.f / GG);
    float var = ss * (1.f / GG) - m * m;
    float rs = rsqrtf(var + 1e-5f);
    float ga = gamma2[c], be = beta2[c];
    for (int g = 0; g < GG; g++)
        g_xo[g * 576 + c] = ga * (g_Hg[g * 576 + c] - m) * rs + be;
}

__global__ void tw1_kernel(const float* __restrict__ w1) {
    int idx = blockIdx.x * 256 + threadIdx.x;
    if (idx >= 384 * 576) return;
    int o = idx / 576, k = idx - o * 576;
    g_w1t[k * 384 + o] = w1[idx];
}

__global__ void tw2_kernel(const float* __restrict__ w2) {
    int idx = blockIdx.x * 256 + threadIdx.x;
    if (idx >= 192 * 384) return;
    int o = idx / 384, k = idx - o * 384;
    g_w2t[k * 192 + o] = w2[idx];
}

__global__ void f1_kernel(const float* __restrict__ b1) {  // grid 16, block 384
    __shared__ float xs[4][576];
    int t = threadIdx.x;
    int g0 = blockIdx.x * 4;
    for (int i = t; i < 4 * 576; i += 384) xs[i / 576][i % 576] = g_xo[(g0 + i / 576) * 576 + (i % 576)];
    __syncthreads();
    float a0 = 0.f, a1 = 0.f, a2 = 0.f, a3 = 0.f;
    for (int k = 0; k < 576; k++) {
        float w = g_w1t[k * 384 + t];
        a0 += xs[0][k] * w; a1 += xs[1][k] * w; a2 += xs[2][k] * w; a3 += xs[3][k] * w;
    }
    float bb = b1[t];
    g_o1[(g0 + 0) * 384 + t] = fmaxf(a0 + bb, 0.f);
    g_o1[(g0 + 1) * 384 + t] = fmaxf(a1 + bb, 0.f);
    g_o1[(g0 + 2) * 384 + t] = fmaxf(a2 + bb, 0.f);
    g_o1[(g0 + 3) * 384 + t] = fmaxf(a3 + bb, 0.f);
}

__global__ void f2_kernel(const float* __restrict__ b2) {  // grid 16, block 192
    __shared__ float xs[4][384];
    int t = threadIdx.x;
    int g0 = blockIdx.x * 4;
    for (int i = t; i < 4 * 384; i += 192) xs[i / 384][i % 384] = g_o1[(g0 + i / 384) * 384 + (i % 384)];
    __syncthreads();
    float a0 = 0.f, a1 = 0.f, a2 = 0.f, a3 = 0.f;
    for (int k = 0; k < 384; k++) {
        float w = g_w2t[k * 192 + t];
        a0 += xs[0][k] * w; a1 += xs[1][k] * w; a2 += xs[2][k] * w; a3 += xs[3][k] * w;
    }
    float bb = b2[t];
    g_o2[(g0 + 0) * 192 + t] = fmaxf(a0 + bb, 0.f);
    g_o2[(g0 + 1) * 192 + t] = fmaxf(a1 + bb, 0.f);
    g_o2[(g0 + 2) * 192 + t] = fmaxf(a2 + bb, 0.f);
    g_o2[(g0 + 3) * 192 + t] = fmaxf(a3 + bb, 0.f);
}

__global__ void f3_kernel(const float* __restrict__ w3, const float* __restrict__ b3,
                          float* __restrict__ out) {  // grid 64, block 32
    int g = blockIdx.x, lane = threadIdx.x;
    float l = -INFINITY;
    if (lane < NC) {
        float a = b3[lane];
        for (int k = 0; k < 192; k++) a += g_o2[g * 192 + k] * w3[lane * 192 + k];
        l = a;
    }
    float m = l;
    #pragma unroll
    for (int o = 16; o; o >>= 1) m = fmaxf(m, __shfl_xor_sync(0xffffffffu, m, o));
    float e = (lane < NC) ? expf(l - m) : 0.f;
    float s = e;
    #pragma unroll
    for (int o = 16; o; o >>= 1) s += __shfl_xor_sync(0xffffffffu, s, o);
    if (lane < NC) out[g * NC + lane] = l - m - logf(s);
}

// ---------------- launch ----------------
extern "C" void kernel_launch(void* const* d_in, const int* in_sizes, int n_in,
                              void* d_out, int out_size) {
    const float* x     = (const float*)d_in[0];
    const void*  ei    = d_in[1];
    const void*  batch = d_in[2];
    const float* W     = (const float*)d_in[3];
    const float* b     = (const float*)d_in[4];
    const float* u     = (const float*)d_in[5];
    const float* g1    = (const float*)d_in[6];
    const float* be1   = (const float*)d_in[7];
    const float* g2    = (const float*)d_in[8];
    const float* be2   = (const float*)d_in[9];
    const float* w1    = (const float*)d_in[10];
    const float* b1    = (const float*)d_in[11];
    const float* w2    = (const float*)d_in[12];
    const float* b2    = (const float*)d_in[13];
    const float* w3    = (const float*)d_in[14];
    const float* b3    = (const float*)d_in[15];
    float* out = (float*)d_out;

    detect_kernel<<<1, 1>>>(ei);
    zero_kernel<<<(GG * DK + 255) / 256, 256>>>();
    deg_kernel<<<EE / 256, 256>>>(ei);
    dinv_kernel<<<NN / 256, 256>>>();
    scan_kernel<<<1, 1024>>>();
    csr_kernel<<<EE / 256, 256>>>(ei);
    spmm_kernel<0><<<NN / 8, 256>>>(x);
    spmm_kernel<1><<<NN / 8, 256>>>(x);
    wprep_kernel<<<1, 256>>>(W, u);
    {
        dim3 grid(3, NN / 64);
        gemm_kernel<<<grid, 256>>>(x, b);
    }
    bnstats_kernel<<<NN / 128, DK>>>();
    bnfin_kernel<<<1, DK>>>();
    pool_kernel<<<(NN * DK) / 256, 256>>>(batch, g1, be1);
    hg_kernel<<<(GG * 576 + 255) / 256, 256>>>();
    bn2_kernel<<<1, 576>>>(g2, be2);
    tw1_kernel<<<(384 * 576 + 255) / 256, 256>>>(w1);
    tw2_kernel<<<(192 * 384 + 255) / 256, 256>>>(w2);
    f1_kernel<<<16, 384>>>(b1);
    f2_kernel<<<16, 192>>>(b2);
    f3_kernel<<<GG, 32>>>(w3, b3, out);
}

// round 10
// speedup vs baseline: 1.4094x; 1.4094x over previous
#include <cuda_runtime.h>
#include <cuda_bf16.h>
#include <math.h>

#define NN 8192
#define EE 262144
#define INC 64
#define DK 192      // IN_C*K = OUT_C*K
#define GG 64
#define NC 10
#define NEG_HUGE (-3.402823466e38f)

// ---------------- static scratch ----------------
__device__ int   g_is64;                  // 1 if index tensors are int64, 0 if int32
__device__ int   g_degi[NN];
__device__ float g_dinv[NN];
__device__ int   g_rowstart[NN + 1];
__device__ int   g_rowpos[NN];
__device__ int   g_gstart[GG];            // first row of each graph (NN if empty)
__device__ __align__(16) int   g_col[EE];
__device__ __align__(16) float g_val[EE];
__device__ __align__(16) float g_H2[NN * INC];
__device__ __align__(16) float g_H3[NN * INC];
__device__ __align__(16) float g_H[NN * DK];
__device__ __align__(16) float g_Wmt[DK * DK];   // transposed masked/scaled weight [k][o]
__device__ float g_csum[DK], g_csumsq[DK];
__device__ __align__(16) float g_Hg[GG * 576];
__device__ __align__(16) float g_w1t[576 * 384];
__device__ __align__(16) float g_w2t[384 * 192];

// index accessor: handles both int32 and int64 on-disk layouts
__device__ __forceinline__ int idx_at(const void* p, long long i) {
    if (g_is64) return (int)(((const long long*)p)[i]);
    return ((const int*)p)[i];
}

// ================= K1: prep =================
// blocks 0..47: zero scratch; all blocks: strided w1/w2 transpose;
// block 48: dtype detect; block 49: spectral-norm + mask -> g_Wmt.
#define TW_TOTAL (384 * 576 + 192 * 384)   // 294912
__global__ void prep_kernel(const void* __restrict__ ei,
                            const float* __restrict__ W, const float* __restrict__ u,
                            const float* __restrict__ w1, const float* __restrict__ w2) {
    __shared__ float v[DK];
    __shared__ float red[256];
    __shared__ float s_nrm, s_inv;
    int blk = blockIdx.x, t = threadIdx.x;

    for (int idx = blk * 256 + t; idx < TW_TOTAL; idx += gridDim.x * 256) {
        if (idx < 384 * 576) {
            int o = idx / 576, k = idx - o * 576;
            g_w1t[k * 384 + o] = w1[idx];
        } else {
            int j = idx - 384 * 576;
            int o = j / 384, k = j - o * 384;
            g_w2t[k * 192 + o] = w2[j];
        }
    }

    if (blk < 48) {
        int i = blk * 256 + t;
        if (i < NN) { g_degi[i] = 0; g_rowpos[i] = 0; }
        if (i < DK) { g_csum[i] = 0.f; g_csumsq[i] = 0.f; }
        if (i < GG) g_gstart[i] = NN;
    } else if (blk == 48) {
        if (t == 0) {
            const int* p = (const int*)ei;
            int zeros = 0;
            for (int i = 0; i < 64; i++)
                if (p[2 * i + 1] == 0) zeros++;
            g_is64 = (zeros >= 48) ? 1 : 0;
        }
    } else if (blk == 49) {
        // ---- wprep: v = W^T u ; normalize ; sigma = u.(W v) ; masked scale ----
        if (t < DK) {
            float a = 0.f;
            for (int i = 0; i < DK; i++) a += W[i * DK + t] * u[i];
            v[t] = a;
        }
        __syncthreads();
        red[t] = (t < DK) ? v[t] * v[t] : 0.f;
        __syncthreads();
        for (int s = 128; s > 0; s >>= 1) { if (t < s) red[t] += red[t + s]; __syncthreads(); }
        if (t == 0) s_nrm = sqrtf(red[0]) + 1e-12f;
        __syncthreads();
        if (t < DK) v[t] /= s_nrm;
        __syncthreads();
        float p = 0.f;
        if (t < DK) {
            float a = 0.f;
            for (int j = 0; j < DK; j++) a += W[t * DK + j] * v[j];
            p = a * u[t];
        }
        red[t] = p;
        __syncthreads();
        for (int s = 128; s > 0; s >>= 1) { if (t < s) red[t] += red[t + s]; __syncthreads(); }
        if (t == 0) s_inv = 1.0f / red[0];
        __syncthreads();
        for (int idx = t; idx < DK * DK; idx += 256) {
            int o = idx / DK, k = idx - o * DK;
            float mv = (k < 64 * ((o >> 6) + 1)) ? W[idx] * s_inv : 0.f;
            g_Wmt[k * DK + o] = mv;
        }
    }
}

// ================= K2: degrees + graph boundaries =================
__global__ void deg_kernel(const void* __restrict__ ei, const void* __restrict__ batch) {
    int e = blockIdx.x * 256 + threadIdx.x;
    if (e < EE) atomicAdd(&g_degi[idx_at(ei, e)], 1);
    if (e < NN) {
        int b = idx_at(batch, e);
        if (e == 0 || idx_at(batch, e - 1) != b) g_gstart[b] = e;
    }
}

// ================= K3: scan + dinv (1 block, 1024 threads) =================
__global__ void scan_kernel() {
    __shared__ int sh[1024];
    int t = threadIdx.x;
    int base = t * 8;
    int loc[8];
    int s = 0;
    #pragma unroll
    for (int i = 0; i < 8; i++) {
        int d = g_degi[base + i];
        loc[i] = s; s += d;
        g_dinv[base + i] = (d > 0) ? rsqrtf((float)d) : 0.f;
    }
    sh[t] = s;
    __syncthreads();
    for (int off = 1; off < 1024; off <<= 1) {
        int v = (t >= off) ? sh[t - off] : 0;
        __syncthreads();
        sh[t] += v;
        __syncthreads();
    }
    int offset = (t > 0) ? sh[t - 1] : 0;
    #pragma unroll
    for (int i = 0; i < 8; i++) g_rowstart[base + i] = offset + loc[i];
    if (t == 1023) g_rowstart[NN] = sh[1023];
}

// ================= K4: CSR build =================
__global__ void csr_kernel(const void* __restrict__ ei) {
    int e = blockIdx.x * 256 + threadIdx.x;
    if (e >= EE) return;
    int r = idx_at(ei, e);
    int c = idx_at(ei, (long long)EE + e);
    int pos = atomicAdd(&g_rowpos[r], 1);
    int at = g_rowstart[r] + pos;
    g_col[at] = c;
    g_val[at] = -g_dinv[r] * g_dinv[c];
}

// ================= K5/K6: SpMM  out = L @ in =================
template <int PASS>
__global__ void spmm_kernel(const float* __restrict__ x) {
    const float* hin  = (PASS == 0) ? x : (const float*)g_H2;
    float*       hout = (PASS == 0) ? g_H2 : g_H3;
    int warp = threadIdx.x >> 5, lane = threadIdx.x & 31;
    int r = blockIdx.x * 8 + warp;
    const float2* in2 = (const float2*)hin;
    float2 acc = in2[r * 32 + lane];
    int s = g_rowstart[r], e = g_rowstart[r + 1];
    for (int base = s; base < e; base += 32) {
        int j = base + lane;
        int c = 0; float v = 0.f;
        if (j < e) { c = g_col[j]; v = g_val[j]; }
        int m = min(32, e - base);
        for (int q = 0; q < m; q++) {
            int cc = __shfl_sync(0xffffffffu, c, q);
            float vv = __shfl_sync(0xffffffffu, v, q);
            float2 xv = in2[cc * 32 + lane];
            acc.x += vv * xv.x;
            acc.y += vv * xv.y;
        }
    }
    ((float2*)hout)[r * 32 + lane] = acc;
}

// ================= K7: masked GEMM + BN1-stats epilogue =================
// BM=64 BN=64 BK=16, 256 threads, 4x4 microtile.
__global__ void gemm_kernel(const float* __restrict__ x, const float* __restrict__ bias) {
    __shared__ __align__(16) float As[16][68];
    __shared__ __align__(16) float Bs[16][68];
    int bx = blockIdx.x, by = blockIdx.y;
    int t = threadIdx.x;
    int kmax = 64 * (bx + 1);
    int tx = t & 15, ty = t >> 4;
    int row0 = by * 64;
    float acc[4][4];
    #pragma unroll
    for (int i = 0; i < 4; i++)
        #pragma unroll
        for (int j = 0; j < 4; j++) acc[i][j] = 0.f;

    int ar = t >> 2, ak4 = t & 3;
    int bo = t & 63, bk = t >> 6;

    for (int k0 = 0; k0 < kmax; k0 += 16) {
        const float* A = (k0 < 64) ? x : (k0 < 128) ? (const float*)g_H2 : (const float*)g_H3;
        int kl = k0 & 63;
        float4 av = *(const float4*)&A[(row0 + ar) * 64 + kl + ak4 * 4];
        As[ak4 * 4 + 0][ar] = av.x;
        As[ak4 * 4 + 1][ar] = av.y;
        As[ak4 * 4 + 2][ar] = av.z;
        As[ak4 * 4 + 3][ar] = av.w;
        #pragma unroll
        for (int i = 0; i < 4; i++) {
            int kk = bk * 4 + i;
            Bs[kk][bo] = g_Wmt[(k0 + kk) * DK + bx * 64 + bo];
        }
        __syncthreads();
        #pragma unroll
        for (int kk = 0; kk < 16; kk++) {
            float4 a = *(float4*)&As[kk][ty * 4];
            float4 bb = *(float4*)&Bs[kk][tx * 4];
            acc[0][0] += a.x * bb.x; acc[0][1] += a.x * bb.y; acc[0][2] += a.x * bb.z; acc[0][3] += a.x * bb.w;
            acc[1][0] += a.y * bb.x; acc[1][1] += a.y * bb.y; acc[1][2] += a.y * bb.z; acc[1][3] += a.y * bb.w;
            acc[2][0] += a.z * bb.x; acc[2][1] += a.z * bb.y; acc[2][2] += a.z * bb.z; acc[2][3] += a.z * bb.w;
            acc[3][0] += a.w * bb.x; acc[3][1] += a.w * bb.y; acc[3][2] += a.w * bb.z; acc[3][3] += a.w * bb.w;
        }
        __syncthreads();
    }
    float4 bv = *(const float4*)&bias[bx * 64 + tx * 4];
    float bj[4] = {bv.x, bv.y, bv.z, bv.w};
    float s[4] = {0.f, 0.f, 0.f, 0.f}, ssq[4] = {0.f, 0.f, 0.f, 0.f};
    #pragma unroll
    for (int i = 0; i < 4; i++) {
        int r = row0 + ty * 4 + i;
        float* dst = &g_H[r * DK + bx * 64 + tx * 4];
        #pragma unroll
        for (int j = 0; j < 4; j++) {
            float val = acc[i][j] + bj[j];
            dst[j] = val;
            s[j] += val;
            ssq[j] += val * val;
        }
    }
    // column reduce across ty (16 groups) via shared, then atomics (spread)
    #pragma unroll
    for (int j = 0; j < 4; j++) { As[ty][tx * 4 + j] = s[j]; Bs[ty][tx * 4 + j] = ssq[j]; }
    __syncthreads();
    if (t < 64) {
        float a = 0.f, b2 = 0.f;
        #pragma unroll
        for (int i = 0; i < 16; i++) { a += As[i][t]; b2 += Bs[i][t]; }
        atomicAdd(&g_csum[bx * 64 + t], a);
        atomicAdd(&g_csumsq[bx * 64 + t], b2);
    }
}

// ================= K8: segmented pool (batch is sorted) =================
// grid GG, block DK. BN1 applied inline; writes avg/sum/max thirds of g_Hg.
__global__ void pool_kernel(const float* __restrict__ gamma, const float* __restrict__ beta) {
    int g = blockIdx.x, c = threadIdx.x;
    float m = g_csum[c] * (1.f / NN);
    float var = g_csumsq[c] * (1.f / NN) - m * m;
    float rs = rsqrtf(var + 1e-5f);
    float ga = gamma[c];
    float a = ga * rs, d = beta[c] - ga * m * rs;

    int s = g_gstart[g];
    float sum = 0.f, mx = NEG_HUGE, cnt = 0.f;
    if (s != NN) {
        int e = NN;
        for (int gg = g + 1; gg < GG; gg++) {
            int st = g_gstart[gg];
            if (st != NN) { e = st; break; }
        }
        int r = s;
        for (; r + 4 <= e; r += 4) {
            float h0 = g_H[(r + 0) * DK + c];
            float h1 = g_H[(r + 1) * DK + c];
            float h2 = g_H[(r + 2) * DK + c];
            float h3 = g_H[(r + 3) * DK + c];
            float v0 = a * h0 + d, v1 = a * h1 + d, v2 = a * h2 + d, v3 = a * h3 + d;
            sum += (v0 + v1) + (v2 + v3);
            mx = fmaxf(mx, fmaxf(fmaxf(v0, v1), fmaxf(v2, v3)));
        }
        for (; r < e; r++) {
            float v = a * g_H[r * DK + c] + d;
            sum += v; mx = fmaxf(mx, v);
        }
        cnt = (float)(e - s);
    }
    g_Hg[g * 576 + c]          = sum / fmaxf(cnt, 1.f);
    g_Hg[g * 576 + DK + c]     = sum;
    g_Hg[g * 576 + 2 * DK + c] = mx;
}

// ================= K9: funnel head (bn2 + f1 + f2 + f3) =================
// grid GG, block 384. bn2 stats recomputed per block (cheap, L2-resident).
__global__ void funnel_kernel(const float* __restrict__ g2, const float* __restrict__ be2,
                              const float* __restrict__ b1, const float* __restrict__ b2,
                              const float* __restrict__ w3, const float* __restrict__ b3,
                              float* __restrict__ out) {
    __shared__ float xs[576];
    __shared__ float o1s[384];
    __shared__ float o2s[192];
    int g = blockIdx.x, t = threadIdx.x;

    for (int c = t; c < 576; c += 384) {
        float s = 0.f, ss = 0.f;
        for (int gg = 0; gg < GG; gg++) {
            float v = g_Hg[gg * 576 + c];
            s += v; ss += v * v;
        }
        float m = s * (1.f / GG);
        float var = ss * (1.f / GG) - m * m;
        float rs = rsqrtf(var + 1e-5f);
        xs[c] = g2[c] * (g_Hg[g * 576 + c] - m) * rs + be2[c];
    }
    __syncthreads();

    {
        float a = b1[t];
        for (int k = 0; k < 576; k++) a += xs[k] * g_w1t[k * 384 + t];
        o1s[t] = fmaxf(a, 0.f);
    }
    __syncthreads();

    if (t < 192) {
        float a = b2[t];
        for (int k = 0; k < 384; k++) a += o1s[k] * g_w2t[k * 192 + t];
        o2s[t] = fmaxf(a, 0.f);
    }
    __syncthreads();

    if (t < 32) {
        int lane = t;
        float l = -INFINITY;
        if (lane < NC) {
            float a = b3[lane];
            for (int k = 0; k < 192; k++) a += o2s[k] * w3[lane * 192 + k];
            l = a;
        }
        float m = l;
        #pragma unroll
        for (int o = 16; o; o >>= 1) m = fmaxf(m, __shfl_xor_sync(0xffffffffu, m, o));
        float e = (lane < NC) ? expf(l - m) : 0.f;
        float s = e;
        #pragma unroll
        for (int o = 16; o; o >>= 1) s += __shfl_xor_sync(0xffffffffu, s, o);
        if (lane < NC) out[g * NC + lane] = l - m - logf(s);
    }
}

// ---------------- launch ----------------
extern "C" void kernel_launch(void* const* d_in, const int* in_sizes, int n_in,
                              void* d_out, int out_size) {
    const float* x     = (const float*)d_in[0];
    const void*  ei    = d_in[1];
    const void*  batch = d_in[2];
    const float* W     = (const float*)d_in[3];
    const float* b     = (const float*)d_in[4];
    const float* u     = (const float*)d_in[5];
    const float* g1    = (const float*)d_in[6];
    const float* be1   = (const float*)d_in[7];
    const float* g2    = (const float*)d_in[8];
    const float* be2   = (const float*)d_in[9];
    const float* w1    = (const float*)d_in[10];
    const float* b1    = (const float*)d_in[11];
    const float* w2    = (const float*)d_in[12];
    const float* b2    = (const float*)d_in[13];
    const float* w3    = (const float*)d_in[14];
    const float* b3    = (const float*)d_in[15];
    float* out = (float*)d_out;

    prep_kernel<<<TW_TOTAL / 256, 256>>>(ei, W, u, w1, w2);   // 1152 blocks
    deg_kernel<<<EE / 256, 256>>>(ei, batch);
    scan_kernel<<<1, 1024>>>();
    csr_kernel<<<EE / 256, 256>>>(ei);
    spmm_kernel<0><<<NN / 8, 256>>>(x);
    spmm_kernel<1><<<NN / 8, 256>>>(x);
    {
        dim3 grid(3, NN / 64);
        gemm_kernel<<<grid, 256>>>(x, b);
    }
    pool_kernel<<<GG, DK>>>(g1, be1);
    funnel_kernel<<<GG, 384>>>(g2, be2, b1, b2, w3, b3, out);
}